// round 6
// baseline (speedup 1.0000x reference)
// Re-run of Round 5 kernel (audited clean; prior bench died in infra with no
// harness output). mma.sync fp16 fused dual-GEMM + cross-wg SMEM reduction.
#include <cuda_runtime.h>
#include <cuda_fp16.h>
#include <cstdint>

// Problem dims
#define NB 8192
#define ND 2048
#define NM 8
#define NC 1000
#define NCP 1024          // padded C

// fp16 scratch (static device memory — allocation-free)
__device__ __half g_xh[(size_t)NB * ND];            // [B][D]
__device__ __half g_wt[(size_t)NM * NCP * ND];      // [m][c][d]  (K-major per (m,c))
__device__ __half g_rwt[(size_t)NM * NCP * ND];     // [m][c][d]

#define SWZ(x) ((x) ^ (((x) >> 3) & 0x70))

__device__ __forceinline__ uint32_t smem_u32(const void* p) {
    uint32_t a;
    asm("{ .reg .u64 t; cvta.to.shared.u64 t, %1; cvt.u32.u64 %0, t; }" : "=r"(a) : "l"(p));
    return a;
}
__device__ __forceinline__ void cp16(uint32_t dst, const void* src) {
    asm volatile("cp.async.cg.shared.global [%0], [%1], 16;" :: "r"(dst), "l"(src));
}
__device__ __forceinline__ void ldsm4(uint32_t* r, uint32_t addr) {
    asm volatile("ldmatrix.sync.aligned.m8n8.x4.shared.b16 {%0,%1,%2,%3}, [%4];"
                 : "=r"(r[0]), "=r"(r[1]), "=r"(r[2]), "=r"(r[3]) : "r"(addr));
}
__device__ __forceinline__ void mma16816(float* d, const uint32_t* a, const uint32_t* b) {
    asm volatile("mma.sync.aligned.m16n8k16.row.col.f32.f16.f16.f32 "
                 "{%0,%1,%2,%3}, {%4,%5,%6,%7}, {%8,%9}, {%0,%1,%2,%3};"
                 : "+f"(d[0]), "+f"(d[1]), "+f"(d[2]), "+f"(d[3])
                 : "r"(a[0]), "r"(a[1]), "r"(a[2]), "r"(a[3]), "r"(b[0]), "r"(b[1]));
}

// ---------------- conversion kernels ----------------
__global__ void cvt_x_kernel(const float* __restrict__ x) {
    size_t i = ((size_t)blockIdx.x * blockDim.x + threadIdx.x) * 4;
    float4 v = *(const float4*)(x + i);
    __half2 h0 = __floats2half2_rn(v.x, v.y);
    __half2 h1 = __floats2half2_rn(v.z, v.w);
    __half2* p = (__half2*)(g_xh + i);
    p[0] = h0; p[1] = h1;
}

// W[m,d,c] -> g_wt[m][c][d]  (pad c to 1024 with zeros)
__global__ void cvt_w_kernel(const float* __restrict__ W) {
    __shared__ float tile[32][33];
    int m = blockIdx.z, d0 = blockIdx.x * 32, c0 = blockIdx.y * 32;
    #pragma unroll
    for (int i = 0; i < 4; i++) {
        int d = d0 + threadIdx.y + i * 8;
        int c = c0 + threadIdx.x;
        float v = (c < NC) ? W[((size_t)m * ND + d) * NC + c] : 0.f;
        tile[threadIdx.y + i * 8][threadIdx.x] = v;
    }
    __syncthreads();
    #pragma unroll
    for (int i = 0; i < 4; i++) {
        int c = c0 + threadIdx.y + i * 8;
        int d = d0 + threadIdx.x;
        g_wt[((size_t)m * NCP + c) * ND + d] = __float2half(tile[threadIdx.x][threadIdx.y + i * 8]);
    }
}

// RW[d, m*1000+c] -> g_rwt[m][c][d]
__global__ void cvt_rw_kernel(const float* __restrict__ RW) {
    __shared__ float tile[32][33];
    int m = blockIdx.z, d0 = blockIdx.x * 32, c0 = blockIdx.y * 32;
    #pragma unroll
    for (int i = 0; i < 4; i++) {
        int d = d0 + threadIdx.y + i * 8;
        int c = c0 + threadIdx.x;
        float v = (c < NC) ? RW[(size_t)d * (NM * NC) + m * NC + c] : 0.f;
        tile[threadIdx.y + i * 8][threadIdx.x] = v;
    }
    __syncthreads();
    #pragma unroll
    for (int i = 0; i < 4; i++) {
        int c = c0 + threadIdx.y + i * 8;
        int d = d0 + threadIdx.x;
        g_rwt[((size_t)m * NCP + c) * ND + d] = __float2half(tile[threadIdx.x][threadIdx.y + i * 8]);
    }
}

// ---------------- fused dual-GEMM (mma.sync) ----------------
// CTA tile: 128 b x 16 c, 16 (m,mat) subtiles = 256 virtual N.
// 8 warps = 2 row-halves x 4 groups; warp owns 64 rows x 4 subtiles
// ({W,R} x {m=2g, 2g+1}). Each warp's fused partial (its 2 m-terms) goes to
// SMEM; a cross-wg reduction produces the final sum over all 8 m.
// K-stage = 64 halves (128B rows, XOR-swizzled). 4-stage cp.async pipeline.

#define NSTAGE      4
#define STAGE_BYTES 49152                    // A 16KB + B 32KB
#define SMEM_TOTAL  (NSTAGE * STAGE_BYTES)   // 196608
#define PSTRIDE     18                       // floats per row in partial buf

__device__ __forceinline__ void load_stage(uint32_t sbase, int stg, int kblk,
                                           int b0, int c0, int tid) {
    const uint32_t sa = sbase + stg * STAGE_BYTES;
    const uint32_t sb = sa + 16384;
    const int k0 = kblk * 64;
    // A: 128 rows x 8 x 16B chunks = 1024 chunks
    #pragma unroll
    for (int i = 0; i < 4; i++) {
        int ch = tid + i * 256;
        int row = ch >> 3, c16 = ch & 7;
        cp16(sa + SWZ(row * 128 + c16 * 16),
             g_xh + (size_t)(b0 + row) * ND + k0 + c16 * 8);
    }
    // B: 16 subtiles x 16 rows x 8 chunks = 2048 chunks
    #pragma unroll
    for (int i = 0; i < 8; i++) {
        int ch = tid + i * 256;
        int t = ch >> 7;                 // subtile 0..15 (0-7 = W, 8-15 = R)
        int w = ch & 127;
        int row = w >> 3, c16 = w & 7;
        const __half* src = (t < 8) ? g_wt : g_rwt;
        cp16(sb + t * 2048 + SWZ(row * 128 + c16 * 16),
             src + ((size_t)(t & 7) * NCP + (c0 + row)) * ND + k0 + c16 * 8);
    }
    asm volatile("cp.async.commit_group;" ::: "memory");
}

__global__ void __launch_bounds__(256, 1)
gemm_kernel(const float* __restrict__ mbias, const float* __restrict__ rbias,
            float* __restrict__ out) {
    extern __shared__ char smem[];
    uint32_t sbase = smem_u32(smem);
    int tid = threadIdx.x;
    int lane = tid & 31;
    int wid = tid >> 5;
    int wr = wid & 1;           // row half: rows [wr*64, wr*64+64)
    int wg = wid >> 1;          // subtile group: m in {2wg, 2wg+1}
    int b0 = blockIdx.x * 128;  // b fast-varying: wave shares B operand
    int c0 = blockIdx.y * 16;

    float acc[4][4][2][4];      // [tile: W0,W1,R0,R1][mfrag][nfrag][4]
    #pragma unroll
    for (int t = 0; t < 4; t++)
        #pragma unroll
        for (int mi = 0; mi < 4; mi++)
            #pragma unroll
            for (int nf = 0; nf < 2; nf++)
                #pragma unroll
                for (int j = 0; j < 4; j++) acc[t][mi][nf][j] = 0.f;

    // prologue: 3 stages in flight
    load_stage(sbase, 0, 0, b0, c0, tid);
    load_stage(sbase, 1, 1, b0, c0, tid);
    load_stage(sbase, 2, 2, b0, c0, tid);

    const int r0 = wr * 64;
    // ldmatrix per-lane offsets (pre-swizzle), constant across stages
    // A x4: lanes 0-15 rows m0..15 @k0, lanes 16-31 same rows @k0+8
    const uint32_t a_lrow = (uint32_t)(r0 + (lane & 15)) * 128 + (uint32_t)(lane >> 4) * 16;
    // B x4: row(c) = (l&7) + 8*((l>>4)&1), khalf = (l>>3)&1
    const uint32_t b_lrow = (uint32_t)((lane & 7) + ((lane >> 4) & 1) * 8) * 128 +
                            (uint32_t)((lane >> 3) & 1) * 16;

    for (int i = 0; i < 32; i++) {
        if (i < 30)      asm volatile("cp.async.wait_group 2;" ::: "memory");
        else if (i == 30) asm volatile("cp.async.wait_group 1;" ::: "memory");
        else             asm volatile("cp.async.wait_group 0;" ::: "memory");
        __syncthreads();

        const uint32_t Ao = sbase + (i & 3) * STAGE_BYTES;
        const uint32_t Bo = Ao + 16384;
        #pragma unroll
        for (int ks = 0; ks < 4; ks++) {
            uint32_t a[4][4];
            #pragma unroll
            for (int mi = 0; mi < 4; mi++)
                ldsm4(a[mi], Ao + SWZ(a_lrow + mi * 16 * 128 + ks * 32));
            #pragma unroll
            for (int tt = 0; tt < 4; tt++) {
                const int t = 2 * wg + (tt & 1) + (tt >> 1) * 8;  // W0,W1,R0,R1
                uint32_t b[4];
                ldsm4(b, Bo + t * 2048 + SWZ(b_lrow + ks * 32));
                #pragma unroll
                for (int mi = 0; mi < 4; mi++) {
                    mma16816(acc[tt][mi][0], a[mi], b);
                    mma16816(acc[tt][mi][1], a[mi], b + 2);
                }
            }
        }
        if (i + 3 < 32) load_stage(sbase, (i + 3) & 3, i + 3, b0, c0, tid);
    }

    // ---- fused partial per warp -> SMEM, then reduce over the 4 wg ----
    __syncthreads();   // stage buffers done; reuse SMEM as partial buffer
    float* buf = (float*)smem;   // [4 wg][128 rows][PSTRIDE]  (36,864 B)

    const int m0 = 2 * wg, m1 = 2 * wg + 1;
    #pragma unroll
    for (int nf = 0; nf < 2; nf++) {
        const int c = c0 + nf * 8 + 2 * (lane & 3);
        float2 bw0 = make_float2(0.f, 0.f), bw1 = bw0, br0 = bw0, br1 = bw0;
        if (c < NC) {   // c even, NC even -> float2 stays in bounds
            bw0 = *(const float2*)(mbias + m0 * NC + c);
            bw1 = *(const float2*)(mbias + m1 * NC + c);
            br0 = *(const float2*)(rbias + m0 * NC + c);
            br1 = *(const float2*)(rbias + m1 * NC + c);
        }
        #pragma unroll
        for (int mi = 0; mi < 4; mi++) {
            const int row = r0 + 16 * mi + (lane >> 2);
            const int cl = nf * 8 + 2 * (lane & 3);
            float2 lo, hi;
            lo.x = (acc[0][mi][nf][0] + bw0.x) * (acc[2][mi][nf][0] + br0.x) +
                   (acc[1][mi][nf][0] + bw1.x) * (acc[3][mi][nf][0] + br1.x);
            lo.y = (acc[0][mi][nf][1] + bw0.y) * (acc[2][mi][nf][1] + br0.y) +
                   (acc[1][mi][nf][1] + bw1.y) * (acc[3][mi][nf][1] + br1.y);
            hi.x = (acc[0][mi][nf][2] + bw0.x) * (acc[2][mi][nf][2] + br0.x) +
                   (acc[1][mi][nf][2] + bw1.x) * (acc[3][mi][nf][2] + br1.x);
            hi.y = (acc[0][mi][nf][3] + bw0.y) * (acc[2][mi][nf][3] + br0.y) +
                   (acc[1][mi][nf][3] + bw1.y) * (acc[3][mi][nf][3] + br1.y);
            *(float2*)(buf + ((wg * 128 + row) * PSTRIDE + cl))     = lo;
            *(float2*)(buf + ((wg * 128 + row + 8) * PSTRIDE + cl)) = hi;
        }
    }
    __syncthreads();

    // reduction: thread -> (row = tid>>1, c half = tid&1), 8 columns
    {
        const int row = tid >> 1;
        const int ch = (tid & 1) * 8;
        float v[8];
        #pragma unroll
        for (int j = 0; j < 8; j++)
            v[j] = buf[(0 * 128 + row) * PSTRIDE + ch + j];
        #pragma unroll
        for (int g = 1; g < 4; g++)
            #pragma unroll
            for (int j = 0; j < 8; j++)
                v[j] += buf[(g * 128 + row) * PSTRIDE + ch + j];

        const size_t obase = (size_t)(b0 + row) * NC;
        #pragma unroll
        for (int q = 0; q < 2; q++) {
            int c = c0 + ch + q * 4;
            if (c + 4 <= NC) {
                *(float4*)(out + obase + c) =
                    make_float4(v[q * 4], v[q * 4 + 1], v[q * 4 + 2], v[q * 4 + 3]);
            } else {
                #pragma unroll
                for (int j = 0; j < 4; j++)
                    if (c + j < NC) out[obase + c + j] = v[q * 4 + j];
            }
        }
    }
}

// ---------------- launch ----------------
extern "C" void kernel_launch(void* const* d_in, const int* in_sizes, int n_in,
                              void* d_out, int out_size) {
    const float* x  = (const float*)d_in[0];
    const float* W  = (const float*)d_in[1];
    const float* mb = (const float*)d_in[2];
    const float* RW = (const float*)d_in[3];
    const float* rb = (const float*)d_in[4];
    float* out = (float*)d_out;

    cudaFuncSetAttribute(gemm_kernel, cudaFuncAttributeMaxDynamicSharedMemorySize, SMEM_TOTAL);

    cvt_x_kernel<<<(NB * ND / 4) / 256, 256>>>(x);
    dim3 tb(32, 8);
    cvt_w_kernel<<<dim3(ND / 32, NCP / 32, NM), tb>>>(W);
    cvt_rw_kernel<<<dim3(ND / 32, NCP / 32, NM), tb>>>(RW);

    gemm_kernel<<<dim3(64, 63), 256, SMEM_TOTAL>>>(mb, rb, out);
}

// round 8
// speedup vs baseline: 1.0085x; 1.0085x over previous
// Re-run of Round 6 kernel (audited: no hang path; prior bench died in infra
// with no harness output — same flake signature as round 5, which passed on
// re-run). mma.sync fp16 fused dual-GEMM; k=128 double-buffered stages
// (2x96KB), post-barrier prefetch, b-fragment hoisting.
#include <cuda_runtime.h>
#include <cuda_fp16.h>
#include <cstdint>

// Problem dims
#define NB 8192
#define ND 2048
#define NM 8
#define NC 1000
#define NCP 1024          // padded C

// fp16 scratch (static device memory — allocation-free)
__device__ __half g_xh[(size_t)NB * ND];            // [B][D]
__device__ __half g_wt[(size_t)NM * NCP * ND];      // [m][c][d]  (K-major per (m,c))
__device__ __half g_rwt[(size_t)NM * NCP * ND];     // [m][c][d]

#define SWZ(x) ((x) ^ (((x) >> 3) & 0x70))

__device__ __forceinline__ uint32_t smem_u32(const void* p) {
    uint32_t a;
    asm("{ .reg .u64 t; cvta.to.shared.u64 t, %1; cvt.u32.u64 %0, t; }" : "=r"(a) : "l"(p));
    return a;
}
__device__ __forceinline__ void cp16(uint32_t dst, const void* src) {
    asm volatile("cp.async.cg.shared.global [%0], [%1], 16;" :: "r"(dst), "l"(src));
}
__device__ __forceinline__ void ldsm4(uint32_t* r, uint32_t addr) {
    asm volatile("ldmatrix.sync.aligned.m8n8.x4.shared.b16 {%0,%1,%2,%3}, [%4];"
                 : "=r"(r[0]), "=r"(r[1]), "=r"(r[2]), "=r"(r[3]) : "r"(addr));
}
__device__ __forceinline__ void mma16816(float* d, const uint32_t* a, const uint32_t* b) {
    asm volatile("mma.sync.aligned.m16n8k16.row.col.f32.f16.f16.f32 "
                 "{%0,%1,%2,%3}, {%4,%5,%6,%7}, {%8,%9}, {%0,%1,%2,%3};"
                 : "+f"(d[0]), "+f"(d[1]), "+f"(d[2]), "+f"(d[3])
                 : "r"(a[0]), "r"(a[1]), "r"(a[2]), "r"(a[3]), "r"(b[0]), "r"(b[1]));
}

// ---------------- conversion kernels ----------------
__global__ void cvt_x_kernel(const float* __restrict__ x) {
    size_t i = ((size_t)blockIdx.x * blockDim.x + threadIdx.x) * 4;
    float4 v = *(const float4*)(x + i);
    __half2 h0 = __floats2half2_rn(v.x, v.y);
    __half2 h1 = __floats2half2_rn(v.z, v.w);
    __half2* p = (__half2*)(g_xh + i);
    p[0] = h0; p[1] = h1;
}

// W[m,d,c] -> g_wt[m][c][d]  (pad c to 1024 with zeros)
__global__ void cvt_w_kernel(const float* __restrict__ W) {
    __shared__ float tile[32][33];
    int m = blockIdx.z, d0 = blockIdx.x * 32, c0 = blockIdx.y * 32;
    #pragma unroll
    for (int i = 0; i < 4; i++) {
        int d = d0 + threadIdx.y + i * 8;
        int c = c0 + threadIdx.x;
        float v = (c < NC) ? W[((size_t)m * ND + d) * NC + c] : 0.f;
        tile[threadIdx.y + i * 8][threadIdx.x] = v;
    }
    __syncthreads();
    #pragma unroll
    for (int i = 0; i < 4; i++) {
        int c = c0 + threadIdx.y + i * 8;
        int d = d0 + threadIdx.x;
        g_wt[((size_t)m * NCP + c) * ND + d] = __float2half(tile[threadIdx.x][threadIdx.y + i * 8]);
    }
}

// RW[d, m*1000+c] -> g_rwt[m][c][d]
__global__ void cvt_rw_kernel(const float* __restrict__ RW) {
    __shared__ float tile[32][33];
    int m = blockIdx.z, d0 = blockIdx.x * 32, c0 = blockIdx.y * 32;
    #pragma unroll
    for (int i = 0; i < 4; i++) {
        int d = d0 + threadIdx.y + i * 8;
        int c = c0 + threadIdx.x;
        float v = (c < NC) ? RW[(size_t)d * (NM * NC) + m * NC + c] : 0.f;
        tile[threadIdx.y + i * 8][threadIdx.x] = v;
    }
    __syncthreads();
    #pragma unroll
    for (int i = 0; i < 4; i++) {
        int c = c0 + threadIdx.y + i * 8;
        int d = d0 + threadIdx.x;
        g_rwt[((size_t)m * NCP + c) * ND + d] = __float2half(tile[threadIdx.x][threadIdx.y + i * 8]);
    }
}

// ---------------- fused dual-GEMM (mma.sync) ----------------
// CTA tile: 128 b x 16 c, 16 (m,mat) subtiles = 256 virtual N.
// 8 warps = 2 row-halves x 4 groups; warp owns 64 rows x 4 subtiles
// ({W,R} x {m=2g, 2g+1}). Cross-wg SMEM reduction sums the 8 m-terms.
// Stage = k128 as two k64 halves (each: A 16KB swizzled + B 16x2KB subtiles).
// 2-stage double buffer; prefetch issued right after the stage barrier.

#define HALF_BYTES  49152                    // A 16KB + B 32KB (one k64 half)
#define STAGE_BYTES (2 * HALF_BYTES)         // 98304 (k128)
#define SMEM_TOTAL  (2 * STAGE_BYTES)        // 196608
#define PSTRIDE     18                       // floats per row in partial buf

// load one k64 half-stage (identical layout to the proven R5 stage)
__device__ __forceinline__ void load_half(uint32_t hbase, int kblk64,
                                          int b0, int c0, int tid) {
    const uint32_t sa = hbase;
    const uint32_t sb = hbase + 16384;
    const int k0 = kblk64 * 64;
    // A: 128 rows x 8 x 16B chunks = 1024 chunks
    #pragma unroll
    for (int i = 0; i < 4; i++) {
        int ch = tid + i * 256;
        int row = ch >> 3, c16 = ch & 7;
        cp16(sa + SWZ(row * 128 + c16 * 16),
             g_xh + (size_t)(b0 + row) * ND + k0 + c16 * 8);
    }
    // B: 16 subtiles x 16 rows x 8 chunks = 2048 chunks
    #pragma unroll
    for (int i = 0; i < 8; i++) {
        int ch = tid + i * 256;
        int t = ch >> 7;                 // subtile 0..15 (0-7 = W, 8-15 = R)
        int w = ch & 127;
        int row = w >> 3, c16 = w & 7;
        const __half* src = (t < 8) ? g_wt : g_rwt;
        cp16(sb + t * 2048 + SWZ(row * 128 + c16 * 16),
             src + ((size_t)(t & 7) * NCP + (c0 + row)) * ND + k0 + c16 * 8);
    }
}

__device__ __forceinline__ void load_stage(uint32_t sbase, int slot, int kpair,
                                           int b0, int c0, int tid) {
    const uint32_t base = sbase + slot * STAGE_BYTES;
    load_half(base,              kpair * 2,     b0, c0, tid);
    load_half(base + HALF_BYTES, kpair * 2 + 1, b0, c0, tid);
    asm volatile("cp.async.commit_group;" ::: "memory");
}

__global__ void __launch_bounds__(256, 1)
gemm_kernel(const float* __restrict__ mbias, const float* __restrict__ rbias,
            float* __restrict__ out) {
    extern __shared__ char smem[];
    uint32_t sbase = smem_u32(smem);
    int tid = threadIdx.x;
    int lane = tid & 31;
    int wid = tid >> 5;
    int wr = wid & 1;           // row half: rows [wr*64, wr*64+64)
    int wg = wid >> 1;          // subtile group: m in {2wg, 2wg+1}
    int b0 = blockIdx.x * 128;  // b fast-varying: wave shares B operand
    int c0 = blockIdx.y * 16;

    float acc[4][4][2][4];      // [tile: W0,W1,R0,R1][mfrag][nfrag][4]
    #pragma unroll
    for (int t = 0; t < 4; t++)
        #pragma unroll
        for (int mi = 0; mi < 4; mi++)
            #pragma unroll
            for (int nf = 0; nf < 2; nf++)
                #pragma unroll
                for (int j = 0; j < 4; j++) acc[t][mi][nf][j] = 0.f;

    // prologue: stage 0 in flight
    load_stage(sbase, 0, 0, b0, c0, tid);

    const int r0 = wr * 64;
    // ldmatrix per-lane offsets (pre-swizzle), constant across stages
    const uint32_t a_lrow = (uint32_t)(r0 + (lane & 15)) * 128 + (uint32_t)(lane >> 4) * 16;
    const uint32_t b_lrow = (uint32_t)((lane & 7) + ((lane >> 4) & 1) * 8) * 128 +
                            (uint32_t)((lane >> 3) & 1) * 16;

    for (int i = 0; i < 16; i++) {
        asm volatile("cp.async.wait_group 0;" ::: "memory");
        __syncthreads();
        // barrier proved slot (i+1)&1 (stage i-1) is drained by all warps
        if (i + 1 < 16) load_stage(sbase, (i + 1) & 1, i + 1, b0, c0, tid);

        #pragma unroll
        for (int h = 0; h < 2; h++) {
            const uint32_t Ao = sbase + (i & 1) * STAGE_BYTES + h * HALF_BYTES;
            const uint32_t Bo = Ao + 16384;
            #pragma unroll
            for (int ks = 0; ks < 4; ks++) {
                uint32_t a[4][4];
                #pragma unroll
                for (int mi = 0; mi < 4; mi++)
                    ldsm4(a[mi], Ao + SWZ(a_lrow + mi * 16 * 128 + ks * 32));
                uint32_t bf[4][4];
                #pragma unroll
                for (int tt = 0; tt < 4; tt++) {
                    const int t = 2 * wg + (tt & 1) + (tt >> 1) * 8;  // W0,W1,R0,R1
                    ldsm4(bf[tt], Bo + t * 2048 + SWZ(b_lrow + ks * 32));
                }
                #pragma unroll
                for (int tt = 0; tt < 4; tt++)
                    #pragma unroll
                    for (int mi = 0; mi < 4; mi++) {
                        mma16816(acc[tt][mi][0], a[mi], bf[tt]);
                        mma16816(acc[tt][mi][1], a[mi], bf[tt] + 2);
                    }
            }
        }
    }

    // ---- fused partial per warp -> SMEM, then reduce over the 4 wg ----
    __syncthreads();   // stage buffers done; reuse SMEM as partial buffer
    float* buf = (float*)smem;   // [4 wg][128 rows][PSTRIDE]  (36,864 B)

    const int m0 = 2 * wg, m1 = 2 * wg + 1;
    #pragma unroll
    for (int nf = 0; nf < 2; nf++) {
        const int c = c0 + nf * 8 + 2 * (lane & 3);
        float2 bw0 = make_float2(0.f, 0.f), bw1 = bw0, br0 = bw0, br1 = bw0;
        if (c < NC) {   // c even, NC even -> float2 stays in bounds
            bw0 = *(const float2*)(mbias + m0 * NC + c);
            bw1 = *(const float2*)(mbias + m1 * NC + c);
            br0 = *(const float2*)(rbias + m0 * NC + c);
            br1 = *(const float2*)(rbias + m1 * NC + c);
        }
        #pragma unroll
        for (int mi = 0; mi < 4; mi++) {
            const int row = r0 + 16 * mi + (lane >> 2);
            const int cl = nf * 8 + 2 * (lane & 3);
            float2 lo, hi;
            lo.x = (acc[0][mi][nf][0] + bw0.x) * (acc[2][mi][nf][0] + br0.x) +
                   (acc[1][mi][nf][0] + bw1.x) * (acc[3][mi][nf][0] + br1.x);
            lo.y = (acc[0][mi][nf][1] + bw0.y) * (acc[2][mi][nf][1] + br0.y) +
                   (acc[1][mi][nf][1] + bw1.y) * (acc[3][mi][nf][1] + br1.y);
            hi.x = (acc[0][mi][nf][2] + bw0.x) * (acc[2][mi][nf][2] + br0.x) +
                   (acc[1][mi][nf][2] + bw1.x) * (acc[3][mi][nf][2] + br1.x);
            hi.y = (acc[0][mi][nf][3] + bw0.y) * (acc[2][mi][nf][3] + br0.y) +
                   (acc[1][mi][nf][3] + bw1.y) * (acc[3][mi][nf][3] + br1.y);
            *(float2*)(buf + ((wg * 128 + row) * PSTRIDE + cl))     = lo;
            *(float2*)(buf + ((wg * 128 + row + 8) * PSTRIDE + cl)) = hi;
        }
    }
    __syncthreads();

    // reduction: thread -> (row = tid>>1, c half = tid&1), 8 columns
    {
        const int row = tid >> 1;
        const int ch = (tid & 1) * 8;
        float v[8];
        #pragma unroll
        for (int j = 0; j < 8; j++)
            v[j] = buf[(0 * 128 + row) * PSTRIDE + ch + j];
        #pragma unroll
        for (int g = 1; g < 4; g++)
            #pragma unroll
            for (int j = 0; j < 8; j++)
                v[j] += buf[(g * 128 + row) * PSTRIDE + ch + j];

        const size_t obase = (size_t)(b0 + row) * NC;
        #pragma unroll
        for (int q = 0; q < 2; q++) {
            int c = c0 + ch + q * 4;
            if (c + 4 <= NC) {
                *(float4*)(out + obase + c) =
                    make_float4(v[q * 4], v[q * 4 + 1], v[q * 4 + 2], v[q * 4 + 3]);
            } else {
                #pragma unroll
                for (int j = 0; j < 4; j++)
                    if (c + j < NC) out[obase + c + j] = v[q * 4 + j];
            }
        }
    }
}

// ---------------- launch ----------------
extern "C" void kernel_launch(void* const* d_in, const int* in_sizes, int n_in,
                              void* d_out, int out_size) {
    const float* x  = (const float*)d_in[0];
    const float* W  = (const float*)d_in[1];
    const float* mb = (const float*)d_in[2];
    const float* RW = (const float*)d_in[3];
    const float* rb = (const float*)d_in[4];
    float* out = (float*)d_out;

    cudaFuncSetAttribute(gemm_kernel, cudaFuncAttributeMaxDynamicSharedMemorySize, SMEM_TOTAL);

    cvt_x_kernel<<<(NB * ND / 4) / 256, 256>>>(x);
    dim3 tb(32, 8);
    cvt_w_kernel<<<dim3(ND / 32, NCP / 32, NM), tb>>>(W);
    cvt_rw_kernel<<<dim3(ND / 32, NCP / 32, NM), tb>>>(RW);

    gemm_kernel<<<dim3(64, 63), 256, SMEM_TOTAL>>>(mb, rb, out);
}